// round 13
// baseline (speedup 1.0000x reference)
#include <cuda_runtime.h>
#include <cuda_bf16.h>
#include <math.h>
#include <stdint.h>

#define B_  32
#define T_  128
#define V_  16000
#define E_  512
#define H_  1024
#define F_  2048
#define G4  4096   // 4*H
#define KC  3072   // 3*H contraction length (B-side [hi|lo|hi])
#define KA  2048   // A-side storage [hi|lo]
#define KE  1536   // 3*E (xproj, both sides stored full)
#define NBLK 128   // persistent LSTM blocks

// ---------------- scratch (device globals: no allocation allowed) ----------
__device__ float g_pooled[B_ * F_];
__device__ float g_bsum[G4];
__device__ int   g_idx[B_ * T_];
__device__ float g_xproj[(size_t)B_ * T_ * G4];        // 67 MB
__device__ __nv_bfloat16 g_A2[(size_t)B_ * T_ * KA];   // 16.8 MB [hi|lo]
__device__ __nv_bfloat16 g_B2[(size_t)V_ * KC];        // 98 MB  [hi|lo|hi]
__device__ __nv_bfloat16 g_W2[(size_t)G4 * KC];        // 25 MB  [hi|lo|hi]
__device__ __nv_bfloat16 g_E2[(size_t)V_ * KE];        // 49 MB  [hi|hi|lo]
__device__ __nv_bfloat16 g_I2[(size_t)G4 * KE];        // 12.6MB [hi|lo|hi]
__device__ __nv_bfloat16 g_A0[B_ * KA];                // h0 split [hi|lo]
__device__ unsigned int  g_barcnt;

// ---------------- cp.async helpers ---------------------------------------------
#define CP_ASYNC16(dst, src) \
    asm volatile("cp.async.cg.shared.global [%0], [%1], 16;" \
                 :: "r"((uint32_t)(dst)), "l"(src))
#define CP_COMMIT() asm volatile("cp.async.commit_group;" ::: "memory")
#define CP_WAIT0()  asm volatile("cp.async.wait_group 0;" ::: "memory")
#define CP_WAIT1()  asm volatile("cp.async.wait_group 1;" ::: "memory")

// ---------------- fused pre kernel (launch #1) ----------------------------------
#define NW_  (V_ * H_)
#define NWH  (G4 * H_)
#define NEM  (V_ * E_)
#define NWI  (G4 * E_)
#define CONVTOT (NW_ + NWH + NEM + NWI)
#define CONVBLK ((CONVTOT + 255) / 256)
__global__ void pre_kernel(const float* __restrict__ Wv,
                           const float* __restrict__ W_hh,
                           const float* __restrict__ emb,
                           const float* __restrict__ W_ih,
                           const float* __restrict__ feat,
                           const int* __restrict__ reports,
                           const float* __restrict__ b_ih,
                           const float* __restrict__ b_hh) {
    int bid = blockIdx.x, tid = threadIdx.x;
    if (bid < CONVBLK) {
        int i = bid * 256 + tid;
        const float* S;
        __nv_bfloat16* D;
        int li, sec, style;
        if (i < NW_) {
            S = Wv; D = g_B2; li = i; sec = 1024; style = 1;
        } else if (i < NW_ + NWH) {
            S = W_hh; D = g_W2; li = i - NW_; sec = 1024; style = 1;
        } else if (i < NW_ + NWH + NEM) {
            S = emb; D = g_E2; li = i - NW_ - NWH; sec = 512; style = 0;
        } else if (i < CONVTOT) {
            S = W_ih; D = g_I2; li = i - NW_ - NWH - NEM; sec = 512; style = 1;
        } else return;
        float x = S[li];
        int m = (sec == 1024) ? (li >> 10) : (li >> 9);
        int k = li & (sec - 1);
        __nv_bfloat16 hi = __float2bfloat16(x);
        __nv_bfloat16 lo = __float2bfloat16(x - __bfloat162float(hi));
        __nv_bfloat16* r = D + (size_t)m * (3 * sec);
        if (style == 0) { r[k] = hi; r[k + sec] = hi; r[k + 2 * sec] = lo; }
        else            { r[k] = hi; r[k + sec] = lo; r[k + 2 * sec] = hi; }
    } else if (bid < CONVBLK + 256) {
        int i = (bid - CONVBLK) * 256 + tid;
        const float* p = feat + (size_t)i * 49;
        float s = 0.f;
#pragma unroll
        for (int k = 0; k < 49; k++) s += p[k];
        g_pooled[i] = s * (1.0f / 49.0f);
    } else {
        int j = (bid - CONVBLK - 256) * 256 + tid;
        if (j == 0) g_barcnt = 0u;
        if (j < G4) g_bsum[j] = b_ih[j] + b_hh[j];
        if (j < B_ * T_) g_idx[j] = ((j & (T_ - 1)) == 0) ? 1 : reports[j - 1];
    }
}

// ---------------- mma / ldmatrix helpers ----------------------------------------
__device__ __forceinline__ uint32_t smem_u32(const void* p) {
    uint32_t a;
    asm("{ .reg .u64 t; cvta.to.shared.u64 t, %1; cvt.u32.u64 %0, t; }"
        : "=r"(a) : "l"(p));
    return a;
}
__device__ __forceinline__ void mma_bf16(float* d, const uint32_t* a,
                                         const uint32_t* b) {
    asm volatile(
        "mma.sync.aligned.m16n8k16.row.col.f32.bf16.bf16.f32 "
        "{%0,%1,%2,%3}, {%4,%5,%6,%7}, {%8,%9}, {%0,%1,%2,%3};"
        : "+f"(d[0]), "+f"(d[1]), "+f"(d[2]), "+f"(d[3])
        : "r"(a[0]), "r"(a[1]), "r"(a[2]), "r"(a[3]), "r"(b[0]), "r"(b[1]));
}
__device__ __forceinline__ void ldsm_x4(uint32_t& r0, uint32_t& r1,
                                        uint32_t& r2, uint32_t& r3,
                                        uint32_t addr) {
    asm volatile("ldmatrix.sync.aligned.m8n8.x4.shared.b16 {%0,%1,%2,%3}, [%4];"
                 : "=r"(r0), "=r"(r1), "=r"(r2), "=r"(r3) : "r"(addr));
}
__device__ __forceinline__ float sigmoidf_(float x) {
    return 1.f / (1.f + expf(-x));
}

// ---------------- 128x128 bf16 mma GEMM (xproj) ---------------------------------
template <int KTOT, int AK, bool GATHER>
__global__ void __launch_bounds__(256, 2)
mma_gemm_nt(const __nv_bfloat16* __restrict__ A2,
            const __nv_bfloat16* __restrict__ B2,
            const float* __restrict__ bias,
            float* __restrict__ C, int ncols,
            const int* __restrict__ ridx) {
    __shared__ uint32_t sA[3][128 * 16];
    __shared__ uint32_t sB[3][128 * 16];

    const int NK = KTOT / 32;
    const int TH = (KTOT - AK) / 32;
    int tid = threadIdx.x;
    int lane = tid & 31, w = tid >> 5;
    int g = lane >> 2, tig = lane & 3;
    int wm = w >> 2, wn = w & 3;
    int laneq = lane >> 4;
    int laneh = (lane >> 3) & 1;
    int lane15 = lane & 15, lane7 = lane & 7;

    int m0 = blockIdx.x * 128;
    int n0 = blockIdx.y * 128;

    uint32_t sA0 = smem_u32(sA), sB0 = smem_u32(sB);

    int lrow = tid >> 1;
    int lhalf = tid & 1;
    int ar = GATHER ? ridx[m0 + lrow] : (m0 + lrow);
    const char* pa = (const char*)((const uint4*)(A2 + (size_t)ar * AK) + lhalf * 2);
    const char* pb = (const char*)((const uint4*)(B2 + (size_t)(n0 + lrow) * KTOT) + lhalf * 2);
    int sw = lrow & 6;
    uint32_t st0 = (uint32_t)(((lrow << 4) + (((lhalf * 4 + 0) ^ sw) << 1)) << 2);
    uint32_t st1 = (uint32_t)(((lrow << 4) + (((lhalf * 4 + 2) ^ sw) << 1)) << 2);

    uint32_t aterm[4], aswz[4];
#pragma unroll
    for (int mt = 0; mt < 4; mt++) {
        int rowA = wm * 64 + mt * 16 + lane15;
        aterm[mt] = (uint32_t)rowA * 64u;
        aswz[mt] = (uint32_t)((rowA & 6) >> 1);
    }
    uint32_t bterm[2], bswz[2];
#pragma unroll
    for (int ntp = 0; ntp < 2; ntp++) {
        int rowB = wn * 32 + (2 * ntp + laneq) * 8 + lane7;
        bterm[ntp] = (uint32_t)rowB * 64u;
        bswz[ntp] = (uint32_t)((rowB & 6) >> 1);
    }

    float acc[4][4][4];
#pragma unroll
    for (int i = 0; i < 4; i++)
#pragma unroll
        for (int j = 0; j < 4; j++)
#pragma unroll
            for (int q = 0; q < 4; q++) acc[i][j][q] = 0.f;

#define AIDX(kn_) ((TH == 0) ? (kn_) : (((kn_) < TH) ? (kn_) : (kn_) - TH))
#define GISSUE(kn_, st_) do {                                                \
        int akc_ = AIDX(kn_);                                                \
        const char* pa_ = pa + (size_t)akc_ * 64;                            \
        const char* pb_ = pb + (size_t)(kn_) * 64;                           \
        uint32_t ab_ = sA0 + (uint32_t)(st_) * 8192u;                        \
        uint32_t bb_ = sB0 + (uint32_t)(st_) * 8192u;                        \
        CP_ASYNC16(ab_ + st0, pa_);                                          \
        CP_ASYNC16(ab_ + st1, pa_ + 16);                                     \
        CP_ASYNC16(bb_ + st0, pb_);                                          \
        CP_ASYNC16(bb_ + st1, pb_ + 16);                                     \
        CP_COMMIT();                                                         \
    } while (0)

    GISSUE(0, 0);
    GISSUE(1, 1);

    for (int kc = 0; kc < NK; kc++) {
        int st = kc % 3;
        if (kc + 1 < NK) { CP_WAIT1(); } else { CP_WAIT0(); }
        __syncthreads();
        if (kc + 2 < NK) GISSUE(kc + 2, (kc + 2) % 3);

        uint32_t abase = sA0 + (uint32_t)st * 8192u;
        uint32_t bbase = sB0 + (uint32_t)st * 8192u;
#pragma unroll
        for (int ks = 0; ks < 2; ks++) {
            uint32_t bf[4][2];
            {
                uint32_t segb = (uint32_t)(2 * ks + laneh);
                ldsm_x4(bf[0][0], bf[0][1], bf[1][0], bf[1][1],
                        bbase + bterm[0] + (((segb ^ bswz[0])) << 4));
                ldsm_x4(bf[2][0], bf[2][1], bf[3][0], bf[3][1],
                        bbase + bterm[1] + (((segb ^ bswz[1])) << 4));
            }
            uint32_t sega = (uint32_t)(2 * ks + laneq);
#pragma unroll
            for (int mt = 0; mt < 4; mt++) {
                uint32_t af[4];
                ldsm_x4(af[0], af[1], af[2], af[3],
                        abase + aterm[mt] + (((sega ^ aswz[mt])) << 4));
#pragma unroll
                for (int nt = 0; nt < 4; nt++)
                    mma_bf16(acc[mt][nt], af, bf[nt]);
            }
        }
    }
#undef GISSUE
#undef AIDX

#pragma unroll
    for (int mt = 0; mt < 4; mt++) {
#pragma unroll
        for (int i2 = 0; i2 < 2; i2++) {
            int row = m0 + wm * 64 + mt * 16 + g + i2 * 8;
            float* crow = C + (size_t)row * ncols;
#pragma unroll
            for (int nt = 0; nt < 4; nt++) {
                int col = n0 + wn * 32 + nt * 8 + 2 * tig;
                float b0 = __ldg(&bias[col]);
                float b1 = __ldg(&bias[col + 1]);
                crow[col]     = acc[mt][nt][i2 * 2]     + b0;
                crow[col + 1] = acc[mt][nt][i2 * 2 + 1] + b1;
            }
        }
    }
}

// ---------------- 256x128 bf16 mma GEMM (output projection) ---------------------
// Warp tile 64x64 (8 warps, 4m x 2n). 3-stage cp.async, dynamic smem 72KB, occ 1.
// A stored [hi|lo] (KA), contraction KC with A-hi reuse (TH = 32).
__global__ void __launch_bounds__(256, 1)
mma_gemm_out256(const __nv_bfloat16* __restrict__ A2,
                const __nv_bfloat16* __restrict__ B2,
                const float* __restrict__ bias,
                float* __restrict__ C) {
    extern __shared__ char smem[];
    // layout: A stages 3 x 16KB @0, B stages 3 x 8KB @49152
    const int NK = KC / 32;            // 96
    const int TH = (KC - KA) / 32;     // 32

    int tid = threadIdx.x;
    int lane = tid & 31, w = tid >> 5;
    int g = lane >> 2, tig = lane & 3;
    int wm = w >> 1, wn = w & 1;
    int laneq = lane >> 4;
    int laneh = (lane >> 3) & 1;
    int lane15 = lane & 15, lane7 = lane & 7;

    int m0 = blockIdx.x * 256;
    int n0 = blockIdx.y * 128;

    uint32_t sbase = smem_u32(smem);
    uint32_t sA0 = sbase, sB0 = sbase + 49152u;

    // A loader: thread -> row tid (0..255), 4 segs of 16B per chunk
    const char* pa = (const char*)(A2 + (size_t)(m0 + tid) * KA);
    uint32_t aswl = (uint32_t)((tid & 6) >> 1);
    uint32_t adst0 = (uint32_t)tid * 64u;
    // B loader: row = tid>>1 (0..127), half = tid&1, 2 segs
    int brow = tid >> 1, bhalf = tid & 1;
    const char* pb = (const char*)(B2 + (size_t)(n0 + brow) * KC) + bhalf * 32;
    uint32_t bswl = (uint32_t)((brow & 6) >> 1);
    uint32_t bdst0 = (uint32_t)brow * 64u;
    uint32_t bs0 = (uint32_t)(bhalf * 2);

    uint32_t aterm[4], aswz[4];
#pragma unroll
    for (int mt = 0; mt < 4; mt++) {
        int rowA = wm * 64 + mt * 16 + lane15;
        aterm[mt] = (uint32_t)rowA * 64u;
        aswz[mt] = (uint32_t)((rowA & 6) >> 1);
    }
    uint32_t bterm[4], bswz[4];
#pragma unroll
    for (int ntp = 0; ntp < 4; ntp++) {
        int rowB = wn * 64 + (2 * ntp + laneq) * 8 + lane7;
        bterm[ntp] = (uint32_t)rowB * 64u;
        bswz[ntp] = (uint32_t)((rowB & 6) >> 1);
    }

    float acc[4][8][4];
#pragma unroll
    for (int i = 0; i < 4; i++)
#pragma unroll
        for (int j = 0; j < 8; j++)
#pragma unroll
            for (int q = 0; q < 4; q++) acc[i][j][q] = 0.f;

#define AIDX256(kn_) (((kn_) < TH) ? (kn_) : (kn_) - TH)
#define GISSUE256(kn_, st_) do {                                             \
        const char* pa_ = pa + (size_t)AIDX256(kn_) * 64;                    \
        const char* pb_ = pb + (size_t)(kn_) * 64;                           \
        uint32_t ab_ = sA0 + (uint32_t)(st_) * 16384u + adst0;               \
        uint32_t bb_ = sB0 + (uint32_t)(st_) * 8192u + bdst0;                \
        CP_ASYNC16(ab_ + (((0u) ^ aswl) << 4), pa_);                         \
        CP_ASYNC16(ab_ + (((1u) ^ aswl) << 4), pa_ + 16);                    \
        CP_ASYNC16(ab_ + (((2u) ^ aswl) << 4), pa_ + 32);                    \
        CP_ASYNC16(ab_ + (((3u) ^ aswl) << 4), pa_ + 48);                    \
        CP_ASYNC16(bb_ + (((bs0 + 0u) ^ bswl) << 4), pb_);                   \
        CP_ASYNC16(bb_ + (((bs0 + 1u) ^ bswl) << 4), pb_ + 16);              \
        CP_COMMIT();                                                         \
    } while (0)

    GISSUE256(0, 0);
    GISSUE256(1, 1);

    for (int kc = 0; kc < NK; kc++) {
        int st = kc % 3;
        if (kc + 1 < NK) { CP_WAIT1(); } else { CP_WAIT0(); }
        __syncthreads();
        if (kc + 2 < NK) GISSUE256(kc + 2, (kc + 2) % 3);

        uint32_t abase = sA0 + (uint32_t)st * 16384u;
        uint32_t bbase = sB0 + (uint32_t)st * 8192u;
#pragma unroll
        for (int ks = 0; ks < 2; ks++) {
            uint32_t bf[8][2];
            {
                uint32_t segb = (uint32_t)(2 * ks + laneh);
                ldsm_x4(bf[0][0], bf[0][1], bf[1][0], bf[1][1],
                        bbase + bterm[0] + ((segb ^ bswz[0]) << 4));
                ldsm_x4(bf[2][0], bf[2][1], bf[3][0], bf[3][1],
                        bbase + bterm[1] + ((segb ^ bswz[1]) << 4));
                ldsm_x4(bf[4][0], bf[4][1], bf[5][0], bf[5][1],
                        bbase + bterm[2] + ((segb ^ bswz[2]) << 4));
                ldsm_x4(bf[6][0], bf[6][1], bf[7][0], bf[7][1],
                        bbase + bterm[3] + ((segb ^ bswz[3]) << 4));
            }
            uint32_t sega = (uint32_t)(2 * ks + laneq);
#pragma unroll
            for (int mt = 0; mt < 4; mt++) {
                uint32_t af[4];
                ldsm_x4(af[0], af[1], af[2], af[3],
                        abase + aterm[mt] + ((sega ^ aswz[mt]) << 4));
#pragma unroll
                for (int nt = 0; nt < 8; nt++)
                    mma_bf16(acc[mt][nt], af, bf[nt]);
            }
        }
    }
#undef GISSUE256
#undef AIDX256

#pragma unroll
    for (int mt = 0; mt < 4; mt++) {
#pragma unroll
        for (int i2 = 0; i2 < 2; i2++) {
            int row = m0 + wm * 64 + mt * 16 + g + i2 * 8;
            float* crow = C + (size_t)row * V_;
#pragma unroll
            for (int nt = 0; nt < 8; nt++) {
                int col = n0 + wn * 64 + nt * 8 + 2 * tig;
                float b0 = __ldg(&bias[col]);
                float b1 = __ldg(&bias[col + 1]);
                crow[col]     = acc[mt][nt][i2 * 2]     + b0;
                crow[col + 1] = acc[mt][nt][i2 * 2 + 1] + b1;
            }
        }
    }
}

// ---------------- persistent tensor-core LSTM (launch #3, unchanged) ------------
__global__ void __launch_bounds__(256, 1)
lstm_persistent(const float* __restrict__ fc_W, const float* __restrict__ fc_b) {
    extern __shared__ char smem[];
    uint32_t* sW = (uint32_t*)smem;                    // 64 slabs x 2048B = 128KB
    uint32_t* sA = (uint32_t*)(smem + 131072);         // 3 x 16KB
    float*  Csum = (float*)(smem + 131072);            // overlay

    int tid = threadIdx.x;
    int lane = tid & 31, w = tid >> 5;
    int g = lane >> 2, tig = lane & 3;
    int wm = w >> 2, wk = w & 3;
    int u0 = blockIdx.x * 8;
    int laneq = lane >> 4;
    int laneh = (lane >> 3) & 1;
    int lane15 = lane & 15, lane7 = lane & 7;

    uint32_t sW0 = smem_u32(sW), sA0 = smem_u32(sA);

    {
        int r = tid >> 3, e = tid & 7;
        int grow = ((r >> 3) << 10) + u0 + (r & 7);
        const uint4* wrow = (const uint4*)(g_W2 + (size_t)grow * KC);
        int sw = (r & 6) << 1;
#pragma unroll 4
        for (int j = 0; j < 32; j++) {
            int idx = e + j * 8;
            uint4 v = wrow[idx];
            int s = idx >> 2, q = (idx & 3) * 4;
            *(uint4*)&sW[s * 512 + r * 16 + (q ^ sw)] = v;
        }
    }

    int cb = tid >> 3, cu = tid & 7;
    int uu = u0 + cu;
    float acch = fc_b[uu], accc = fc_b[H_ + uu];
    {
        const float4* pp  = (const float4*)(g_pooled + cb * F_);
        const float4* pwh = (const float4*)(fc_W + (size_t)uu * F_);
        const float4* pwc = (const float4*)(fc_W + (size_t)(H_ + uu) * F_);
#pragma unroll 4
        for (int k = 0; k < F_ / 4; k++) {
            float4 p = pp[k], a = pwh[k], b = pwc[k];
            acch += p.x * a.x + p.y * a.y + p.z * a.z + p.w * a.w;
            accc += p.x * b.x + p.y * b.y + p.z * b.z + p.w * b.w;
        }
    }
    float creg = accc;
    {
        __nv_bfloat16 hi = __float2bfloat16(acch);
        __nv_bfloat16 lo = __float2bfloat16(acch - __bfloat162float(hi));
        __nv_bfloat16* r = g_A0 + cb * KA;
        r[uu] = hi; r[uu + 1024] = lo;
    }

    unsigned epoch = 0;
    unsigned long long barp;
    asm("cvta.global.u64 %0, %1;" : "=l"(barp) : "l"(&g_barcnt));
#define GRIDBAR() do {                                                       \
        __syncthreads();                                                     \
        epoch++;                                                             \
        if (tid == 0) {                                                      \
            asm volatile("red.release.gpu.global.add.u32 [%0], %1;"          \
                         :: "l"(barp), "r"(1u) : "memory");                  \
            unsigned v_;                                                     \
            do {                                                             \
                asm volatile("ld.acquire.gpu.global.u32 %0, [%1];"           \
                             : "=r"(v_) : "l"(barp) : "memory");             \
            } while (v_ < epoch * (unsigned)NBLK);                           \
        }                                                                    \
        __syncthreads();                                                     \
    } while (0)

    GRIDBAR();

    int lr = tid >> 3, le = tid & 7;
    int lsw = (lr & 6) << 1;

    uint32_t adst[4];
    uint32_t asrcoff[4];
#pragma unroll
    for (int j = 0; j < 4; j++) {
        int cu4 = le + j * 8;
        int q = (cu4 & 3) * 4;
        adst[j] = (uint32_t)((cu4 >> 2) * 2048 + lr * 64 + ((q ^ lsw) << 2));
        asrcoff[j] = (uint32_t)(cu4 * 16);
    }

    uint32_t aterm, aswz;
    {
        int rowA = wm * 16 + lane15;
        aterm = (uint32_t)rowA * 64u;
        aswz = (uint32_t)((rowA & 6) >> 1);
    }
    uint32_t wterm[2], wswz[2];
#pragma unroll
    for (int ntp = 0; ntp < 2; ntp++) {
        int rowW = (2 * ntp + laneq) * 8 + lane7;
        wterm[ntp] = (uint32_t)rowW * 64u;
        wswz[ntp] = (uint32_t)((rowW & 6) >> 1);
    }

#define AISSUE(kc_, p_) do {                                                 \
        const char* base_ = abytes + (size_t)(kc_) * 512;                    \
        uint32_t db_ = sA0 + (uint32_t)(p_) * 16384u;                        \
        CP_ASYNC16(db_ + adst[0], base_ + asrcoff[0]);                       \
        CP_ASYNC16(db_ + adst[1], base_ + asrcoff[1]);                       \
        CP_ASYNC16(db_ + adst[2], base_ + asrcoff[2]);                       \
        CP_ASYNC16(db_ + adst[3], base_ + asrcoff[3]);                       \
        CP_COMMIT();                                                         \
    } while (0)

#define LOADFRAG(buf, kc_, jj_, abase_) do {                                  \
        int j16_ = (jj_) * 4 + wk;                                            \
        int s_ = j16_ >> 1, h_ = j16_ & 1;                                    \
        uint32_t slabA_ = (abase_) + (uint32_t)s_ * 2048u;                    \
        uint32_t slabW_ = sW0 + (uint32_t)(((kc_) * 8 + s_) ^ 32) * 2048u;    \
        ldsm_x4(af[buf][0], af[buf][1], af[buf][2], af[buf][3],               \
                slabA_ + aterm + ((((uint32_t)(2 * h_ + laneq)) ^ aswz) << 4));\
        uint32_t segw_ = (uint32_t)(2 * h_ + laneh);                          \
        ldsm_x4(bfA[buf][0][0], bfA[buf][0][1], bfA[buf][1][0], bfA[buf][1][1],\
                slabW_ + wterm[0] + ((segw_ ^ wswz[0]) << 4));                \
        ldsm_x4(bfA[buf][2][0], bfA[buf][2][1], bfA[buf][3][0], bfA[buf][3][1],\
                slabW_ + wterm[1] + ((segw_ ^ wswz[1]) << 4));                \
    } while (0)

    float xp0, xp1, xp2, xp3;
    {
        const float* xp = g_xproj + ((size_t)(cb * T_ + 0)) * G4 + uu;
        xp0 = xp[0]; xp1 = xp[1024]; xp2 = xp[2048]; xp3 = xp[3072];
    }

    for (int t = 0; t < T_; t++) {
        const __nv_bfloat16* Abase =
            (t == 0) ? (g_A0 + lr * KA)
                     : (g_A2 + ((size_t)(lr * T_ + (t - 1))) * KA);
        const char* abytes = (const char*)Abase;

        float acc0[4][4], acc1[4][4];
#pragma unroll
        for (int i = 0; i < 4; i++)
#pragma unroll
            for (int q = 0; q < 4; q++) { acc0[i][q] = 0.f; acc1[i][q] = 0.f; }

        AISSUE(0, 0);
        AISSUE(1, 1);

        for (int kc = 0; kc < 8; kc++) {
            int p = kc % 3;
            if (kc + 1 < 8) { CP_WAIT1(); } else { CP_WAIT0(); }
            __syncthreads();
            if (kc + 2 < 8) AISSUE(kc + 2, (kc + 2) % 3);

            uint32_t abase = sA0 + (uint32_t)p * 16384u;
            uint32_t af[2][4], bfA[2][4][2];
            LOADFRAG(0, kc, 0, abase);
#pragma unroll
            for (int jj = 0; jj < 4; jj++) {
                if (jj < 3) LOADFRAG((jj + 1) & 1, kc, jj + 1, abase);
                int cur = jj & 1;
                float (*accp)[4] = (jj & 1) ? acc1 : acc0;
                if (kc < 4) {
                    int j16 = jj * 4 + wk;
                    int s = j16 >> 1, h = j16 & 1;
                    uint32_t slabW0b = sW0 + (uint32_t)(kc * 8 + s) * 2048u;
                    uint32_t segw = (uint32_t)(2 * h + laneh);
                    uint32_t bfB[4][2];
                    ldsm_x4(bfB[0][0], bfB[0][1], bfB[1][0], bfB[1][1],
                            slabW0b + wterm[0] + ((segw ^ wswz[0]) << 4));
                    ldsm_x4(bfB[2][0], bfB[2][1], bfB[3][0], bfB[3][1],
                            slabW0b + wterm[1] + ((segw ^ wswz[1]) << 4));
#pragma unroll
                    for (int nt = 0; nt < 4; nt++)
                        mma_bf16(accp[nt], af[cur], bfA[cur][nt]);
#pragma unroll
                    for (int nt = 0; nt < 4; nt++)
                        mma_bf16(accp[nt], af[cur], bfB[nt]);
                } else {
#pragma unroll
                    for (int nt = 0; nt < 4; nt++)
                        mma_bf16(accp[nt], af[cur], bfA[cur][nt]);
                }
            }
        }
        __syncthreads();

#pragma unroll
        for (int nt = 0; nt < 4; nt++) {
#pragma unroll
            for (int i2 = 0; i2 < 2; i2++) {
                int m = wm * 16 + g + i2 * 8;
                int n = nt * 8 + 2 * tig;
                Csum[(wk * 32 + m) * 33 + n]     = acc0[nt][i2 * 2]     + acc1[nt][i2 * 2];
                Csum[(wk * 32 + m) * 33 + n + 1] = acc0[nt][i2 * 2 + 1] + acc1[nt][i2 * 2 + 1];
            }
        }
        __syncthreads();

        {
            float gate[4];
#pragma unroll
            for (int g4 = 0; g4 < 4; g4++) {
                int n = g4 * 8 + cu;
                gate[g4] = Csum[(0 * 32 + cb) * 33 + n] + Csum[(1 * 32 + cb) * 33 + n]
                         + Csum[(2 * 32 + cb) * 33 + n] + Csum[(3 * 32 + cb) * 33 + n];
            }
            gate[0] += xp0; gate[1] += xp1; gate[2] += xp2; gate[3] += xp3;
            float cn = sigmoidf_(gate[1]) * creg + sigmoidf_(gate[0]) * tanhf(gate[2]);
            float hn = sigmoidf_(gate[3]) * tanhf(cn);
            creg = cn;
            __nv_bfloat16 hi = __float2bfloat16(hn);
            __nv_bfloat16 lo = __float2bfloat16(hn - __bfloat162float(hi));
            __nv_bfloat16* r = g_A2 + ((size_t)(cb * T_ + t)) * KA;
            r[uu] = hi; r[uu + 1024] = lo;
        }
        if (t + 1 < T_) {
            const float* xp = g_xproj + ((size_t)(cb * T_ + t + 1)) * G4 + uu;
            xp0 = xp[0]; xp1 = xp[1024]; xp2 = xp[2048]; xp3 = xp[3072];
        }
        GRIDBAR();
    }
#undef GRIDBAR
#undef LOADFRAG
#undef AISSUE
}

// ---------------- launcher ---------------------------------------------------------
extern "C" void kernel_launch(void* const* d_in, const int* in_sizes, int n_in,
                              void* d_out, int out_size) {
    const float* features = (const float*)d_in[0];
    const int*   reports  = (const int*)d_in[1];
    const float* fc_W     = (const float*)d_in[2];
    const float* fc_b     = (const float*)d_in[3];
    const float* emb      = (const float*)d_in[4];
    const float* W_ih     = (const float*)d_in[5];
    const float* W_hh     = (const float*)d_in[6];
    const float* b_ih     = (const float*)d_in[7];
    const float* b_hh     = (const float*)d_in[8];
    const float* Wv       = (const float*)d_in[9];
    const float* bv       = (const float*)d_in[10];
    float* out = (float*)d_out;

    float *xproj_p, *bsum_p;
    __nv_bfloat16 *A2_p, *B2_p, *E2_p, *I2_p;
    int* idx_p;
    cudaGetSymbolAddress((void**)&xproj_p,  g_xproj);
    cudaGetSymbolAddress((void**)&bsum_p,   g_bsum);
    cudaGetSymbolAddress((void**)&idx_p,    g_idx);
    cudaGetSymbolAddress((void**)&A2_p,     g_A2);
    cudaGetSymbolAddress((void**)&B2_p,     g_B2);
    cudaGetSymbolAddress((void**)&E2_p,     g_E2);
    cudaGetSymbolAddress((void**)&I2_p,     g_I2);

    cudaFuncSetAttribute(lstm_persistent,
                         cudaFuncAttributeMaxDynamicSharedMemorySize, 180224);
    cudaFuncSetAttribute(mma_gemm_out256,
                         cudaFuncAttributeMaxDynamicSharedMemorySize, 73728);

    // #1: fused pre (conv splits + pooling + prep)
    pre_kernel<<<CONVBLK + 256 + 17, 256>>>(Wv, W_hh, emb, W_ih,
                                            features, reports, b_ih, b_hh);

    // #2: xproj = emb[idx] @ W_ih^T + bsum
    mma_gemm_nt<KE, KE, true><<<dim3((B_ * T_) / 128, G4 / 128), 256>>>(
        E2_p, I2_p, bsum_p, xproj_p, G4, idx_p);

    // #3: persistent tensor-core LSTM
    lstm_persistent<<<NBLK, 256, 180224>>>(fc_W, fc_b);

    // #4: output projection, 256x128 tile / 64x64 warp tile
    mma_gemm_out256<<<dim3((B_ * T_) / 256, V_ / 128), 256, 73728>>>(
        A2_p, B2_p, bv, out);
}